// round 5
// baseline (speedup 1.0000x reference)
#include <cuda_runtime.h>

#define N_SRC 50000
#define N_DST 50000
#define D     128
#define K     8
#define FLAG_IDX (N_SRC + N_DST)   // escape-hatch flag slot (memset-zeroed)

// Scratch (no allocations allowed). One memset covers out_deg + neg + flag.
__device__ int  g_counters[N_SRC + N_DST + 1]; // [0,N_SRC)=out_deg, then neg, then flag
__device__ int  g_ptr[N_DST + 1];
__device__ int  g_flag[N_DST];                 // 1 = 8-pair path, -1 = fallback loop
__device__ int2 g_pairs[N_DST * K];            // (src, weight-bits); (0,0) = pad

// Kernel 0: does ANY source node carry category == -1 ?  (coalesced 200 KB scan)
__global__ void __launch_bounds__(256)
scan_kernel(const int* __restrict__ category, int n_src) {
    int i = blockIdx.x * blockDim.x + threadIdx.x;
    if (i < n_src && __ldg(&category[i]) == -1)
        g_counters[FLAG_IDX] = 1;   // only 1 is ever written: plain store is safe
}

// Kernel 1: out-degree histogram (4 edges/thread, int4 loads) + CSR ptr via
// boundary scan of sorted dst_idx. Per-edge category gather + neg atomics run
// ONLY when the escape-hatch flag is set (never, for normal category data).
__global__ void __launch_bounds__(256)
count_kernel(const int* __restrict__ src_idx,
             const int* __restrict__ dst_idx,
             const int* __restrict__ category, int E) {
    int t = blockIdx.x * blockDim.x + threadIdx.x;
    int e0 = t * 4;
    if (e0 >= E) return;

    if (e0 + 3 < E) {
        int4 s4 = __ldg((const int4*)(src_idx + e0));
        int4 d4 = __ldg((const int4*)(dst_idx + e0));
        atomicAdd(&g_counters[s4.x], 1);
        atomicAdd(&g_counters[s4.y], 1);
        atomicAdd(&g_counters[s4.z], 1);
        atomicAdd(&g_counters[s4.w], 1);

        if (__ldg(&g_counters[FLAG_IDX])) {     // uniform branch; normally 0
            if (__ldg(&category[s4.x]) == -1) atomicAdd(&g_counters[N_SRC + d4.x], 1);
            if (__ldg(&category[s4.y]) == -1) atomicAdd(&g_counters[N_SRC + d4.y], 1);
            if (__ldg(&category[s4.z]) == -1) atomicAdd(&g_counters[N_SRC + d4.z], 1);
            if (__ldg(&category[s4.w]) == -1) atomicAdd(&g_counters[N_SRC + d4.w], 1);
        }

        // ptr[n] = lower_bound(dst_idx, n): for n in (dst[e-1], dst[e]] it's e.
        int dv[5];
        dv[0] = (e0 == 0) ? -1 : __ldg(&dst_idx[e0 - 1]);
        dv[1] = d4.x; dv[2] = d4.y; dv[3] = d4.z; dv[4] = d4.w;
        #pragma unroll
        for (int j = 0; j < 4; ++j)
            for (int d = dv[j] + 1; d <= dv[j + 1]; ++d) g_ptr[d] = e0 + j;
        if (e0 + 4 == E)
            for (int d = d4.w + 1; d <= N_DST; ++d) g_ptr[d] = E;
    } else {
        // Scalar tail (E not divisible by 4)
        int any_neg = __ldg(&g_counters[FLAG_IDX]);
        for (int e = e0; e < E; ++e) {
            int s = __ldg(&src_idx[e]);
            atomicAdd(&g_counters[s], 1);
            int cur = __ldg(&dst_idx[e]);
            if (any_neg && __ldg(&category[s]) == -1)
                atomicAdd(&g_counters[N_SRC + cur], 1);
            int prev = (e == 0) ? -1 : __ldg(&dst_idx[e - 1]);
            for (int d = prev + 1; d <= cur; ++d) g_ptr[d] = e;
            if (e == E - 1)
                for (int d = cur + 1; d <= N_DST; ++d) g_ptr[d] = E;
        }
    }
}

// Kernel 2: resolve sampling per (node,k), one thread each. Octet dedup via
// shuffles: duplicate sampled srcs merged (first occurrence keeps summed
// weight, rest become (0,0) pads -> L1-resident row-0 gathers in main).
__global__ void __launch_bounds__(256)
prep_kernel(const float* __restrict__ unif,
            const int* __restrict__ src_idx, int E) {
    int t = blockIdx.x * blockDim.x + threadIdx.x;
    if (t >= N_DST * K) return;
    int n = t >> 3;
    int k = t & 7;
    int p0 = __ldg(&g_ptr[n]);
    int p1 = __ldg(&g_ptr[n + 1]);
    int deg = p1 - p0;
    bool small = (deg <= K);
    bool full  = small || (__ldg(&g_counters[N_SRC + n]) > 0);
    if (k == 0) g_flag[n] = (full && !small) ? -1 : 1;

    int src = 0;
    float w = 0.f;
    if (!full) {
        float fdeg = (float)deg;
        float u = __ldg(&unif[t]);
        int off = min((int)floorf(u * fdeg), deg - 1);
        int eid = min(p0 + off, E - 1);
        src = __ldg(&src_idx[eid]);
        w = rsqrtf((float)max(__ldg(&g_counters[src]), 1)) * rsqrtf(fdeg);
    } else if (small && k < deg) {
        src = __ldg(&src_idx[p0 + k]);
        w = rsqrtf((float)max(__ldg(&g_counters[src]), 1)) *
            rsqrtf((float)max(deg, 1));
    }

    if (full && !small) return;   // fallback path: pairs unused

    int lane = threadIdx.x & 31;
    int base = lane & ~7;
    float wsum = 0.f;
    int first = k;
    #pragma unroll
    for (int j = 0; j < K; ++j) {
        int   sj = __shfl_sync(0xffffffffu, src, base + j);
        float wj = __shfl_sync(0xffffffffu, w,   base + j);
        if (sj == src) {
            wsum += wj;
            first = min(first, j);
        }
    }
    g_pairs[t] = (first == k) ? make_int2(src, __float_as_int(wsum))
                              : make_int2(0, 0);
}

// Kernel 3: one warp per dst node, barrier-free. 4 broadcast int4 loads of the
// pair block, then 8 independent float4 gathers + store.
__global__ void __launch_bounds__(256)
main_kernel(const float* __restrict__ h_src,
            const int* __restrict__ src_idx,
            float* __restrict__ out) {
    int warp = (blockIdx.x * blockDim.x + threadIdx.x) >> 5;
    int lane = threadIdx.x & 31;
    if (warp >= N_DST) return;
    int n = warp;

    float4 acc = make_float4(0.f, 0.f, 0.f, 0.f);

    if (__ldg(&g_flag[n]) > 0) {
        const int4* pb = (const int4*)(g_pairs + n * K);
        int4 q0 = __ldg(&pb[0]);
        int4 q1 = __ldg(&pb[1]);
        int4 q2 = __ldg(&pb[2]);
        int4 q3 = __ldg(&pb[3]);
        int   srcs[K] = {q0.x, q0.z, q1.x, q1.z, q2.x, q2.z, q3.x, q3.z};
        float ws[K]   = {__int_as_float(q0.y), __int_as_float(q0.w),
                         __int_as_float(q1.y), __int_as_float(q1.w),
                         __int_as_float(q2.y), __int_as_float(q2.w),
                         __int_as_float(q3.y), __int_as_float(q3.w)};
        #pragma unroll
        for (int k = 0; k < K; ++k) {
            const float4* row = (const float4*)(h_src + (long long)srcs[k] * D);
            float4 v = __ldg(&row[lane]);
            float w = ws[k];
            acc.x += v.x * w; acc.y += v.y * w; acc.z += v.z * w; acc.w += v.w * w;
        }
        ((float4*)(out + (long long)n * D))[lane] = acc;
    } else {
        // Escape hatch (neg>0 && deg>K): full reduction over all edges.
        int p0 = __ldg(&g_ptr[n]);
        int p1 = __ldg(&g_ptr[n + 1]);
        int deg = p1 - p0;
        for (int e = p0; e < p1; ++e) {
            int s = __ldg(&src_idx[e]);
            float w = rsqrtf((float)max(__ldg(&g_counters[s]), 1));
            const float4* row = (const float4*)(h_src + (long long)s * D);
            float4 v = __ldg(&row[lane]);
            acc.x += v.x * w; acc.y += v.y * w; acc.z += v.z * w; acc.w += v.w * w;
        }
        float innorm = rsqrtf((float)max(deg, 1));
        float4 o;
        o.x = acc.x * innorm; o.y = acc.y * innorm;
        o.z = acc.z * innorm; o.w = acc.w * innorm;
        ((float4*)(out + (long long)n * D))[lane] = o;
    }
}

extern "C" void kernel_launch(void* const* d_in, const int* in_sizes, int n_in,
                              void* d_out, int out_size) {
    const float* h_src    = (const float*)d_in[0];
    // d_in[1] = h_dst : unused by the reference computation
    const float* unif     = (const float*)d_in[2];
    const int*   src_idx  = (const int*)d_in[3];
    const int*   dst_idx  = (const int*)d_in[4];
    const int*   category = (const int*)d_in[5];
    float* out = (float*)d_out;

    int E = in_sizes[3];
    int n_src = in_sizes[5];

    void* counters_ptr = nullptr;
    cudaGetSymbolAddress(&counters_ptr, g_counters);
    cudaMemsetAsync(counters_ptr, 0, (N_SRC + N_DST + 1) * sizeof(int));

    scan_kernel<<<(n_src + 255) / 256, 256>>>(category, n_src);
    count_kernel<<<((E + 3) / 4 + 255) / 256, 256>>>(src_idx, dst_idx, category, E);
    prep_kernel<<<(N_DST * K + 255) / 256, 256>>>(unif, src_idx, E);
    main_kernel<<<(N_DST * 32 + 255) / 256, 256>>>(h_src, src_idx, out);
}

// round 6
// speedup vs baseline: 1.0738x; 1.0738x over previous
#include <cuda_runtime.h>

#define N_SRC 50000
#define N_DST 50000
#define D     128
#define K     8

// Scratch (no allocations allowed). out_deg and neg fused for one memset.
__device__ int  g_counters[N_SRC + N_DST]; // [0,N_SRC)=out_deg, rest = neg cnt
__device__ int  g_ptr[N_DST + 1];
__device__ int2 g_pairs[N_DST * K];        // (src, weight-bits); (0,0) = pad;
                                           // pair0.src = -1 => fallback path

// Kernel 1: out-degree histogram + escape-hatch counter + CSR ptr via
// boundary scan of the sorted dst_idx.
__global__ void __launch_bounds__(256)
count_kernel(const int* __restrict__ src_idx,
             const int* __restrict__ dst_idx,
             const int* __restrict__ category, int E) {
    int e = blockIdx.x * blockDim.x + threadIdx.x;
    if (e >= E) return;
    int s = __ldg(&src_idx[e]);
    atomicAdd(&g_counters[s], 1);
    int cur = __ldg(&dst_idx[e]);
    if (__ldg(&category[s]) == -1) atomicAdd(&g_counters[N_SRC + cur], 1);
    int prev = (e == 0) ? -1 : __ldg(&dst_idx[e - 1]);
    for (int d = prev + 1; d <= cur; ++d) g_ptr[d] = e;
    if (e == E - 1)
        for (int d = cur + 1; d <= N_DST; ++d) g_ptr[d] = E;
}

// Kernel 2: resolve sampling per (node,k), one thread each (400k threads hide
// the ptr->unif->src_idx->out_deg chain). Octet dedup via shuffles: duplicate
// sampled srcs merged (first occurrence keeps summed weight, rest become
// (0,0) pads -> L1-resident row-0 gathers in main). Both norms folded in.
// Fallback nodes (neg>0 && deg>K, never on sane data) get src=-1 sentinel.
__global__ void __launch_bounds__(256)
prep_kernel(const float* __restrict__ unif,
            const int* __restrict__ src_idx, int E) {
    int t = blockIdx.x * blockDim.x + threadIdx.x;
    if (t >= N_DST * K) return;
    int n = t >> 3;
    int k = t & 7;
    int p0 = __ldg(&g_ptr[n]);
    int p1 = __ldg(&g_ptr[n + 1]);
    int deg = p1 - p0;
    bool small = (deg <= K);
    bool full  = small || (__ldg(&g_counters[N_SRC + n]) > 0);

    if (full && !small) {              // escape hatch: sentinel, pairs unused
        if (k == 0) g_pairs[t] = make_int2(-1, 0);
        return;
    }

    int src = 0;
    float w = 0.f;
    if (!full) {
        float fdeg = (float)deg;
        float u = __ldg(&unif[t]);
        int off = min((int)floorf(u * fdeg), deg - 1);
        int eid = min(p0 + off, E - 1);
        src = __ldg(&src_idx[eid]);
        w = rsqrtf((float)max(__ldg(&g_counters[src]), 1)) * rsqrtf(fdeg);
    } else if (k < deg) {
        src = __ldg(&src_idx[p0 + k]);
        w = rsqrtf((float)max(__ldg(&g_counters[src]), 1)) *
            rsqrtf((float)max(deg, 1));
    }

    int lane = threadIdx.x & 31;
    int base = lane & ~7;
    float wsum = 0.f;
    int first = k;
    #pragma unroll
    for (int j = 0; j < K; ++j) {
        int   sj = __shfl_sync(0xffffffffu, src, base + j);
        float wj = __shfl_sync(0xffffffffu, w,   base + j);
        if (sj == src) {
            wsum += wj;
            first = min(first, j);
        }
    }
    g_pairs[t] = (first == k) ? make_int2(src, __float_as_int(wsum))
                              : make_int2(0, 0);
}

// Kernel 3: one warp per dst node, barrier-free. The ONLY dependent load is
// the 4 broadcast int4 pair loads; the path flag rides in pair0.x's sign.
__global__ void __launch_bounds__(256)
main_kernel(const float* __restrict__ h_src,
            const int* __restrict__ src_idx,
            float* __restrict__ out) {
    int warp = (blockIdx.x * blockDim.x + threadIdx.x) >> 5;  // grid exact
    int lane = threadIdx.x & 31;
    int n = warp;

    const int4* pb = (const int4*)(g_pairs + n * K);
    int4 q0 = __ldg(&pb[0]);
    int4 q1 = __ldg(&pb[1]);
    int4 q2 = __ldg(&pb[2]);
    int4 q3 = __ldg(&pb[3]);

    float4 acc = make_float4(0.f, 0.f, 0.f, 0.f);

    if (q0.x >= 0) {
        int   srcs[K] = {q0.x, q0.z, q1.x, q1.z, q2.x, q2.z, q3.x, q3.z};
        float ws[K]   = {__int_as_float(q0.y), __int_as_float(q0.w),
                         __int_as_float(q1.y), __int_as_float(q1.w),
                         __int_as_float(q2.y), __int_as_float(q2.w),
                         __int_as_float(q3.y), __int_as_float(q3.w)};
        #pragma unroll
        for (int k = 0; k < K; ++k) {
            const float4* row = (const float4*)(h_src + (long long)srcs[k] * D);
            float4 v = __ldg(&row[lane]);
            float w = ws[k];
            acc.x += v.x * w; acc.y += v.y * w; acc.z += v.z * w; acc.w += v.w * w;
        }
        ((float4*)(out + (long long)n * D))[lane] = acc;
    } else {
        // Escape hatch (neg>0 && deg>K): full reduction over all edges.
        int p0 = __ldg(&g_ptr[n]);
        int p1 = __ldg(&g_ptr[n + 1]);
        int deg = p1 - p0;
        for (int e = p0; e < p1; ++e) {
            int s = __ldg(&src_idx[e]);
            float w = rsqrtf((float)max(__ldg(&g_counters[s]), 1));
            const float4* row = (const float4*)(h_src + (long long)s * D);
            float4 v = __ldg(&row[lane]);
            acc.x += v.x * w; acc.y += v.y * w; acc.z += v.z * w; acc.w += v.w * w;
        }
        float innorm = rsqrtf((float)max(deg, 1));
        float4 o;
        o.x = acc.x * innorm; o.y = acc.y * innorm;
        o.z = acc.z * innorm; o.w = acc.w * innorm;
        ((float4*)(out + (long long)n * D))[lane] = o;
    }
}

extern "C" void kernel_launch(void* const* d_in, const int* in_sizes, int n_in,
                              void* d_out, int out_size) {
    const float* h_src    = (const float*)d_in[0];
    // d_in[1] = h_dst : unused by the reference computation
    const float* unif     = (const float*)d_in[2];
    const int*   src_idx  = (const int*)d_in[3];
    const int*   dst_idx  = (const int*)d_in[4];
    const int*   category = (const int*)d_in[5];
    float* out = (float*)d_out;

    int E = in_sizes[3];

    void* counters_ptr = nullptr;
    cudaGetSymbolAddress(&counters_ptr, g_counters);
    cudaMemsetAsync(counters_ptr, 0, (N_SRC + N_DST) * sizeof(int));

    count_kernel<<<(E + 255) / 256, 256>>>(src_idx, dst_idx, category, E);
    prep_kernel<<<(N_DST * K + 255) / 256, 256>>>(unif, src_idx, E);
    main_kernel<<<(N_DST * 32) / 256, 256>>>(h_src, src_idx, out);
}